// round 1
// baseline (speedup 1.0000x reference)
#include <cuda_runtime.h>
#include <cstdint>

// TopKNoisyRouter: fused dual-GEMM + noisy top-2 routing.
//   logits[n,e]  = sum_d x[n,d] * w_route[e,d]
//   nlogit[n,e]  = sum_d x[n,d] * w_noise[e,d]
//   noisy = logits + eps * softplus(nlogit)
//   top-2 over e, softmax over the 2 values, scatter into zeros[N,64].
// Outputs (concatenated in d_out, float32): router_output [N*64], then
// (if out_size large enough) indices [N*2] as float.
//
// GEMM: one fused [N,1024] x [1024,128] (cols 0..63 = route, 64..127 = noise),
// fp32 with packed fma.rn.f32x2 (FFMA2) accumulators for 2x fp32 throughput.

#define DK 1024
#define NE 64
#define BM 128
#define BN 128
#define BK 32
#define SEP 132   // padded smem row stride (floats), 16B-aligned (132*4=528)

typedef unsigned long long ull;

__device__ __forceinline__ void fma2(ull &acc, ull a, ull b) {
    asm("fma.rn.f32x2 %0, %1, %2, %0;" : "+l"(acc) : "l"(a), "l"(b));
}
__device__ __forceinline__ ull dup2(float a) {
    ull r; asm("mov.b64 %0, {%1, %1};" : "=l"(r) : "f"(a)); return r;
}
__device__ __forceinline__ void unpack2(ull v, float &a, float &b) {
    asm("mov.b64 {%0, %1}, %2;" : "=f"(a), "=f"(b) : "l"(v));
}

__device__ __forceinline__ float softplusf(float v) {
    // jax.nn.softplus(x) = max(x,0) + log1p(exp(-|x|))
    return fmaxf(v, 0.0f) + log1pf(expf(-fabsf(v)));
}

__global__ __launch_bounds__(256, 2)
void TopKNoisyRouter_kernel(const float* __restrict__ x,
                            const float* __restrict__ wr,
                            const float* __restrict__ wn,
                            const float* __restrict__ eps,
                            float* __restrict__ out,
                            float* __restrict__ idx_out,
                            int write_idx)
{
    extern __shared__ float smem[];           // 128*SEP floats (67584 B)
    float* xs = smem;                          // compute phase: [BK][SEP]
    float* ws = smem + BK * SEP;               // compute phase: [BK][SEP]

    const int tid = threadIdx.x;
    const int tx  = tid & 15;      // 16 col-groups of 8
    const int ty  = tid >> 4;      // 16 row-groups of 8
    const int row0 = blockIdx.x * BM;

    // ---- coalesced zero-fill of this block's output tile [128 x 64] ----
    {
        float4 z = make_float4(0.f, 0.f, 0.f, 0.f);
        float4* ot = (float4*)(out + (size_t)row0 * NE);
        for (int i = tid; i < BM * NE / 4; i += 256) ot[i] = z;
    }

    ull acc[8][4];
    #pragma unroll
    for (int i = 0; i < 8; ++i)
        #pragma unroll
        for (int j = 0; j < 4; ++j) acc[i][j] = 0ull;

    const int lr = tid >> 3;         // 0..31
    const int kv = (tid & 7) * 4;    // 0,4,...,28

    for (int k0 = 0; k0 < DK; k0 += BK) {
        // ---- load x tile (transposed into xs[k][row]) and w tile ----
        #pragma unroll
        for (int it = 0; it < 4; ++it) {
            int r = it * 32 + lr;
            float4 v = *(const float4*)&x[(size_t)(row0 + r) * DK + k0 + kv];
            xs[(kv + 0) * SEP + r] = v.x;
            xs[(kv + 1) * SEP + r] = v.y;
            xs[(kv + 2) * SEP + r] = v.z;
            xs[(kv + 3) * SEP + r] = v.w;

            int e = it * 32 + lr;
            const float* wp = (e < NE) ? (wr + (size_t)e * DK)
                                       : (wn + (size_t)(e - NE) * DK);
            float4 w4 = *(const float4*)&wp[k0 + kv];
            ws[(kv + 0) * SEP + e] = w4.x;
            ws[(kv + 1) * SEP + e] = w4.y;
            ws[(kv + 2) * SEP + e] = w4.z;
            ws[(kv + 3) * SEP + e] = w4.w;
        }
        __syncthreads();

        // ---- 8x8 microtile, f32x2-packed columns ----
        #pragma unroll
        for (int kk = 0; kk < BK; ++kk) {
            const float* xrow = &xs[kk * SEP + ty * 8];
            const float* wrow = &ws[kk * SEP + tx * 8];
            float4 a0 = *(const float4*)(xrow);
            float4 a1 = *(const float4*)(xrow + 4);
            ull b0 = *(const ull*)(wrow + 0);
            ull b1 = *(const ull*)(wrow + 2);
            ull b2 = *(const ull*)(wrow + 4);
            ull b3 = *(const ull*)(wrow + 6);
            float av[8] = {a0.x, a0.y, a0.z, a0.w, a1.x, a1.y, a1.z, a1.w};
            #pragma unroll
            for (int i = 0; i < 8; ++i) {
                ull ai = dup2(av[i]);
                fma2(acc[i][0], ai, b0);
                fma2(acc[i][1], ai, b1);
                fma2(acc[i][2], ai, b2);
                fma2(acc[i][3], ai, b3);
            }
        }
        __syncthreads();
    }

    // ---- stage accumulators to smem: s[row][col], col 0..63 route, 64..127 noise ----
    float* s = smem;  // reuse full 128*SEP
    #pragma unroll
    for (int i = 0; i < 8; ++i) {
        float* srow = &s[(ty * 8 + i) * SEP + tx * 8];
        #pragma unroll
        for (int j = 0; j < 4; ++j) {
            float a, b;
            unpack2(acc[i][j], a, b);
            srow[2 * j]     = a;
            srow[2 * j + 1] = b;
        }
    }
    __syncthreads();

    // ---- epilogue: one warp per 16 rows; 64 candidates across 32 lanes ----
    const int lane = tid & 31;
    const int warp = tid >> 5;
    const float NEG = __int_as_float(0xff800000);  // -inf

    for (int r = warp * 16; r < warp * 16 + 16; ++r) {
        const size_t n = (size_t)row0 + r;
        const float* srow = &s[r * SEP];
        float lg0 = srow[lane];
        float lg1 = srow[lane + 32];
        float nl0 = srow[64 + lane];
        float nl1 = srow[96 + lane];
        float e0 = eps[n * NE + lane];
        float e1 = eps[n * NE + lane + 32];
        float v0 = lg0 + e0 * softplusf(nl0);
        float v1 = lg1 + e1 * softplusf(nl1);

        // top-1 (ties -> lower index, matching jax.lax.top_k)
        float bv = v0; int bi = lane;
        if (v1 > v0) { bv = v1; bi = lane + 32; }
        #pragma unroll
        for (int off = 16; off; off >>= 1) {
            float ov = __shfl_xor_sync(0xffffffffu, bv, off);
            int   oi = __shfl_xor_sync(0xffffffffu, bi, off);
            if (ov > bv || (ov == bv && oi < bi)) { bv = ov; bi = oi; }
        }
        const float m1v = bv; const int m1i = bi;

        // remove winner, top-2
        float w0 = v0, w1 = v1;
        if (lane == (m1i & 31)) { if (m1i < 32) w0 = NEG; else w1 = NEG; }
        bv = w0; bi = lane;
        if (w1 > w0) { bv = w1; bi = lane + 32; }
        #pragma unroll
        for (int off = 16; off; off >>= 1) {
            float ov = __shfl_xor_sync(0xffffffffu, bv, off);
            int   oi = __shfl_xor_sync(0xffffffffu, bi, off);
            if (ov > bv || (ov == bv && oi < bi)) { bv = ov; bi = oi; }
        }
        const float m2v = bv; const int m2i = bi;

        if (lane == 0) {
            // softmax over {m1v, m2v}, m1v >= m2v
            float ee = expf(m2v - m1v);
            float inv = 1.0f / (1.0f + ee);
            out[n * NE + m1i] = inv;
            out[n * NE + m2i] = ee * inv;
            if (write_idx) {
                idx_out[n * 2 + 0] = (float)m1i;
                idx_out[n * 2 + 1] = (float)m2i;
            }
        }
    }
}

extern "C" void kernel_launch(void* const* d_in, const int* in_sizes, int n_in,
                              void* d_out, int out_size)
{
    const float* x   = (const float*)d_in[0];
    const float* wr  = (const float*)d_in[1];
    const float* wn  = (const float*)d_in[2];
    const float* eps = (const float*)d_in[3];
    float* out = (float*)d_out;

    const int N = in_sizes[3] / NE;            // eps is [N, 64]
    const int write_idx = (out_size >= N * NE + N * 2) ? 1 : 0;
    float* idx_out = out + (size_t)N * NE;

    const int smem_bytes = BM * SEP * sizeof(float);  // 67584
    cudaFuncSetAttribute(TopKNoisyRouter_kernel,
                         cudaFuncAttributeMaxDynamicSharedMemorySize, smem_bytes);
    TopKNoisyRouter_kernel<<<N / BM, 256, smem_bytes>>>(
        x, wr, wn, eps, out, idx_out, write_idx);
}

// round 3
// speedup vs baseline: 1.4102x; 1.4102x over previous
#include <cuda_runtime.h>
#include <cuda_bf16.h>
#include <cstdint>

// TopKNoisyRouter via classic tensor-core mma.sync (compute_103-safe, no 'a'
// features): fused dual GEMM [N,1024]x[1024,128] as 3-way bf16 split
// (6 partial HMMA products, fp32 accum, ~2^-24 accuracy), fused
// noisy-top-2 + softmax epilogue.

#define DK 1024
#define NE 64
#define BM 128
#define KC 64
#define NCHUNK (DK / KC)      // 16
#define PLANE_B 16384         // one 128x64 bf16 tile

// Pre-split weights (route rows 0..63, noise rows 64..127), K-major bf16.
__device__ __nv_bfloat16 g_wb[3][128 * DK];

__device__ __forceinline__ uint32_t smem_u32(const void* p) {
    uint32_t a;
    asm("{ .reg .u64 t; cvta.to.shared.u64 t, %1; cvt.u32.u64 %0, t; }" : "=r"(a) : "l"(p));
    return a;
}
__device__ __forceinline__ void ldsm4(uint32_t& r0, uint32_t& r1, uint32_t& r2,
                                      uint32_t& r3, uint32_t addr) {
    asm volatile("ldmatrix.sync.aligned.m8n8.x4.shared.b16 {%0,%1,%2,%3}, [%4];"
                 : "=r"(r0), "=r"(r1), "=r"(r2), "=r"(r3) : "r"(addr));
}
__device__ __forceinline__ void mma16816(float* c, uint32_t a0, uint32_t a1,
                                         uint32_t a2, uint32_t a3,
                                         uint32_t b0, uint32_t b1) {
    asm volatile("mma.sync.aligned.m16n8k16.row.col.f32.bf16.bf16.f32 "
                 "{%0,%1,%2,%3}, {%4,%5,%6,%7}, {%8,%9}, {%0,%1,%2,%3};"
                 : "+f"(c[0]), "+f"(c[1]), "+f"(c[2]), "+f"(c[3])
                 : "r"(a0), "r"(a1), "r"(a2), "r"(a3), "r"(b0), "r"(b1));
}
__device__ __forceinline__ float softplusf(float v) {
    return fmaxf(v, 0.0f) + log1pf(expf(-fabsf(v)));
}
__device__ __forceinline__ uint32_t pack_bf2(__nv_bfloat16 lo, __nv_bfloat16 hi) {
    return (uint32_t)__bfloat16_as_ushort(lo) | ((uint32_t)__bfloat16_as_ushort(hi) << 16);
}

// ---------------- prep: split weights into 3 bf16 planes ----------------
__global__ void prep_weights(const float* __restrict__ wr, const float* __restrict__ wn) {
    int i = blockIdx.x * blockDim.x + threadIdx.x;    // 0 .. 128*1024-1
    int e = i >> 10, k = i & 1023;
    float v = (e < NE) ? wr[e * DK + k] : wn[(e - NE) * DK + k];
    __nv_bfloat16 b0 = __float2bfloat16(v);
    float r1 = v - __bfloat162float(b0);
    __nv_bfloat16 b1 = __float2bfloat16(r1);
    float r2 = r1 - __bfloat162float(b1);
    g_wb[0][i] = b0;
    g_wb[1][i] = b1;
    g_wb[2][i] = __float2bfloat16(r2);
}

// smem: A planes [0,16K,32K), B planes [48K,64K,80K); epilogue reuse:
//   C [128][130] fp32 at 0 (66560 B), eps [128][66] fp32 at 66560 (33792 B)
#define SMEM_BYTES 100352

__global__ __launch_bounds__(256, 2)
void router_gemm(const float* __restrict__ x, const float* __restrict__ eps,
                 float* __restrict__ out, float* __restrict__ idx_out, int write_idx)
{
    extern __shared__ char smem[];
    const uint32_t sb = smem_u32(smem);
    const uint32_t sbA = sb;
    const uint32_t sbB = sb + 3 * PLANE_B;
    const int tid = threadIdx.x;
    const int lane = tid & 31, wid = tid >> 5;
    const int wm = wid & 1, wn = wid >> 1;       // warp tile: 64x32 at (wm*64, wn*32)
    const int row0 = blockIdx.x * BM;

    // coalesced zero-fill of this block's output tile [128 x 64]
    {
        float4 z = make_float4(0.f, 0.f, 0.f, 0.f);
        float4* ot = (float4*)(out + (size_t)row0 * NE);
        #pragma unroll
        for (int i = 0; i < 8; ++i) ot[tid + 256 * i] = z;
    }

    // ldmatrix per-thread bases (swizzle: column-bytes XOR (row&7)<<4)
    const int rA = wm * 64 + (lane & 15);
    const uint32_t xorA = (uint32_t)((rA & 7) << 4);
    const uint32_t cbA = (uint32_t)((lane >> 4) * 16);
    const int rB = wn * 32 + (lane & 7) + ((lane >> 4) << 3);
    const uint32_t xorB = (uint32_t)((rB & 7) << 4);
    const uint32_t cbB = (uint32_t)(((lane >> 3) & 1) * 16);

    float acc[4][4][4];
    #pragma unroll
    for (int mt = 0; mt < 4; ++mt)
        #pragma unroll
        for (int nt = 0; nt < 4; ++nt)
            #pragma unroll
            for (int q = 0; q < 4; ++q) acc[mt][nt][q] = 0.f;

    const int r_x = tid >> 1;            // x row this thread loads
    const int kh  = (tid & 1) * 32;      // k half

    for (int c = 0; c < NCHUNK; ++c) {
        const int k0 = c * KC;
        if (c) __syncthreads();          // previous mma done before overwrite

        // ---- x: load fp32, 3-way bf16 split, swizzled stores ----
        {
            const float* xr = x + (size_t)(row0 + r_x) * DK + k0 + kh;
            #pragma unroll
            for (int i = 0; i < 8; ++i) {
                float4 v = *(const float4*)(xr + 4 * i);
                uint32_t off = (uint32_t)(r_x * 128 + (kh + 4 * i) * 2);
                uint32_t sw = (off & ~0x70u) | ((off ^ ((uint32_t)(r_x & 7) << 4)) & 0x70u);
                float f[4] = {v.x, v.y, v.z, v.w};
                __nv_bfloat16 s0[4], s1[4], s2[4];
                #pragma unroll
                for (int j = 0; j < 4; ++j) {
                    s0[j] = __float2bfloat16(f[j]);
                    float r1 = f[j] - __bfloat162float(s0[j]);
                    s1[j] = __float2bfloat16(r1);
                    float r2 = r1 - __bfloat162float(s1[j]);
                    s2[j] = __float2bfloat16(r2);
                }
                *(uint2*)(smem + 0 * PLANE_B + sw) =
                    make_uint2(pack_bf2(s0[0], s0[1]), pack_bf2(s0[2], s0[3]));
                *(uint2*)(smem + 1 * PLANE_B + sw) =
                    make_uint2(pack_bf2(s1[0], s1[1]), pack_bf2(s1[2], s1[3]));
                *(uint2*)(smem + 2 * PLANE_B + sw) =
                    make_uint2(pack_bf2(s2[0], s2[1]), pack_bf2(s2[2], s2[3]));
            }
        }

        // ---- B: pre-split bf16 from global (L2-hot), swizzled 16B stores ----
        #pragma unroll
        for (int j = 0; j < 12; ++j) {
            const int u = tid + 256 * j;            // 0..3071
            const int s = u >> 10;
            const int rem = u & 1023;
            const int n = rem >> 3, cu = rem & 7;
            uint4 w = *(const uint4*)&g_wb[s][n * DK + k0 + cu * 8];
            uint32_t off = (uint32_t)(n * 128 + cu * 16);
            uint32_t sw = off ^ (((uint32_t)(n & 7)) << 4);
            *(uint4*)(smem + 3 * PLANE_B + s * PLANE_B + sw) = w;
        }
        __syncthreads();

        // ---- 6 split products, k16 steps ----
        #pragma unroll 1
        for (int ks = 0; ks < 4; ++ks) {
            const uint32_t kb = (uint32_t)(ks * 32);
            #pragma unroll
            for (int pa = 0; pa < 3; ++pa) {
                uint32_t a[4][4];
                #pragma unroll
                for (int mt = 0; mt < 4; ++mt)
                    ldsm4(a[mt][0], a[mt][1], a[mt][2], a[mt][3],
                          sbA + pa * PLANE_B + (rA + mt * 16) * 128 + ((kb + cbA) ^ xorA));
                #pragma unroll
                for (int pb = 0; pb < 3 - pa; ++pb) {
                    uint32_t b[8];
                    ldsm4(b[0], b[1], b[2], b[3],
                          sbB + pb * PLANE_B + rB * 128 + ((kb + cbB) ^ xorB));
                    ldsm4(b[4], b[5], b[6], b[7],
                          sbB + pb * PLANE_B + (rB + 16) * 128 + ((kb + cbB) ^ xorB));
                    #pragma unroll
                    for (int mt = 0; mt < 4; ++mt)
                        #pragma unroll
                        for (int nt = 0; nt < 4; ++nt)
                            mma16816(acc[mt][nt], a[mt][0], a[mt][1], a[mt][2],
                                     a[mt][3], b[2 * nt], b[2 * nt + 1]);
                }
            }
        }
    }
    __syncthreads();

    // ---- stage C to smem [128][130] + eps [128][66], then fused epilogue ----
    float* Cs = (float*)smem;
    float* Es = (float*)(smem + 66560);
    {
        const int crow = wm * 64 + (lane >> 2);
        const int ccol = wn * 32 + (lane & 3) * 2;
        #pragma unroll
        for (int mt = 0; mt < 4; ++mt)
            #pragma unroll
            for (int nt = 0; nt < 4; ++nt) {
                float* p0 = Cs + (crow + mt * 16) * 130 + ccol + nt * 8;
                p0[0] = acc[mt][nt][0]; p0[1] = acc[mt][nt][1];
                float* p1 = p0 + 8 * 130;
                p1[0] = acc[mt][nt][2]; p1[1] = acc[mt][nt][3];
            }
        const float4* eg = (const float4*)(eps + (size_t)row0 * NE);
        #pragma unroll
        for (int i4 = 0; i4 < 8; ++i4) {
            int u = tid + 256 * i4;                 // 0..2047
            float4 v = eg[u];
            int r = u >> 4, e = (u & 15) * 4;
            float* d = Es + r * 66 + e;
            d[0] = v.x; d[1] = v.y; d[2] = v.z; d[3] = v.w;
        }
    }
    __syncthreads();

    if (tid < BM) {
        const int r = tid;
        const size_t n = (size_t)row0 + r;
        const float* lg = Cs + r * 130;
        const float* er = Es + r * 66;
        const float NEG = __int_as_float(0xff800000);
        float m1 = NEG, m2 = NEG; int i1 = 0, i2 = 0;
        #pragma unroll
        for (int e = 0; e < NE; ++e) {
            float v = lg[e] + er[e] * softplusf(lg[e + 64]);
            if (v > m1) { m2 = m1; i2 = i1; m1 = v; i1 = e; }
            else if (v > m2) { m2 = v; i2 = e; }
        }
        float ee = expf(m2 - m1);
        float inv = 1.0f / (1.0f + ee);
        out[n * NE + i1] = inv;
        out[n * NE + i2] = ee * inv;
        if (write_idx) {
            idx_out[n * 2 + 0] = (float)i1;
            idx_out[n * 2 + 1] = (float)i2;
        }
    }
}

extern "C" void kernel_launch(void* const* d_in, const int* in_sizes, int n_in,
                              void* d_out, int out_size)
{
    const float* x   = (const float*)d_in[0];
    const float* wr  = (const float*)d_in[1];
    const float* wn  = (const float*)d_in[2];
    const float* eps = (const float*)d_in[3];
    float* out = (float*)d_out;

    const int N = in_sizes[3] / NE;
    const int write_idx = (out_size >= N * NE + N * 2) ? 1 : 0;
    float* idx_out = out + (size_t)N * NE;

    prep_weights<<<(128 * DK) / 256, 256>>>(wr, wn);

    cudaFuncSetAttribute(router_gemm,
                         cudaFuncAttributeMaxDynamicSharedMemorySize, SMEM_BYTES);
    router_gemm<<<N / BM, 256, SMEM_BYTES>>>(x, eps, out, idx_out, write_idx);
}

// round 4
// speedup vs baseline: 1.8032x; 1.2787x over previous
#include <cuda_runtime.h>
#include <cuda_fp16.h>
#include <cstdint>

// TopKNoisyRouter: fused dual GEMM [N,1024]x[1024,128] via fp16 2-way split
// (3 HMMA products xh*wh + xh*wl + xl*wh, fp32 accum, W pre-scaled by 32 to
// keep w_lo out of fp16 subnormals), cp.async software pipeline, fused
// noisy-top-2 + softmax epilogue.

#define DK 1024
#define NE 64
#define BM 128
#define KC 64
#define NCHUNK (DK / KC)      // 16
#define PLANE_B 16384         // one 128x64 fp16 tile (row = 128B)
#define XROW_B 272            // padded fp32 x-stage row (68 floats)
#define XSTAGE_B (128 * XROW_B)   // 34816

// smem byte offsets
#define OFF_A  0                          // 2 planes (h,l), single-buffered
#define OFF_B  (2 * PLANE_B)              // 2 bufs x 2 planes
#define OFF_X  (OFF_B + 2 * 2 * PLANE_B)  // 2 bufs x XSTAGE_B
#define SMEM_BYTES (OFF_X + 2 * XSTAGE_B) // 167936

// Pre-split scaled weights: g_w[0]=fp16(32w), g_w[1]=fp16(32w - hi). K-major,
// rows 0..63 route, 64..127 noise.
__device__ __half g_w[2][128 * DK];

__device__ __forceinline__ uint32_t smem_u32(const void* p) {
    uint32_t a;
    asm("{ .reg .u64 t; cvta.to.shared.u64 t, %1; cvt.u32.u64 %0, t; }" : "=r"(a) : "l"(p));
    return a;
}
__device__ __forceinline__ void cp16(uint32_t dst, const void* src) {
    asm volatile("cp.async.cg.shared.global [%0], [%1], 16;" :: "r"(dst), "l"(src));
}
__device__ __forceinline__ void ldsm4(uint32_t& r0, uint32_t& r1, uint32_t& r2,
                                      uint32_t& r3, uint32_t addr) {
    asm volatile("ldmatrix.sync.aligned.m8n8.x4.shared.b16 {%0,%1,%2,%3}, [%4];"
                 : "=r"(r0), "=r"(r1), "=r"(r2), "=r"(r3) : "r"(addr));
}
__device__ __forceinline__ void mma16816(float* c, uint32_t a0, uint32_t a1,
                                         uint32_t a2, uint32_t a3,
                                         uint32_t b0, uint32_t b1) {
    asm volatile("mma.sync.aligned.m16n8k16.row.col.f32.f16.f16.f32 "
                 "{%0,%1,%2,%3}, {%4,%5,%6,%7}, {%8,%9}, {%0,%1,%2,%3};"
                 : "+f"(c[0]), "+f"(c[1]), "+f"(c[2]), "+f"(c[3])
                 : "r"(a0), "r"(a1), "r"(a2), "r"(a3), "r"(b0), "r"(b1));
}
__device__ __forceinline__ float softplusf(float v) {
    return fmaxf(v, 0.0f) + log1pf(expf(-fabsf(v)));
}
__device__ __forceinline__ uint32_t pack_h2(__half lo, __half hi) {
    return (uint32_t)__half_as_ushort(lo) | ((uint32_t)__half_as_ushort(hi) << 16);
}

// ---------------- prep: split scaled weights into 2 fp16 planes ----------------
__global__ void prep_weights(const float* __restrict__ wr, const float* __restrict__ wn) {
    int i = blockIdx.x * blockDim.x + threadIdx.x;    // 0 .. 128*1024-1
    int e = i >> 10, k = i & 1023;
    float v = 32.0f * ((e < NE) ? wr[e * DK + k] : wn[(e - NE) * DK + k]);
    __half h = __float2half_rn(v);
    g_w[0][i] = h;
    g_w[1][i] = __float2half_rn(v - __half2float(h));
}

__global__ __launch_bounds__(256, 1)
void router_gemm(const float* __restrict__ x, const float* __restrict__ eps,
                 float* __restrict__ out, float* __restrict__ idx_out, int write_idx)
{
    extern __shared__ char smem[];
    const uint32_t sb = smem_u32(smem);
    const int tid = threadIdx.x;
    const int lane = tid & 31, wid = tid >> 5;
    const int wm = wid & 1, wn = wid >> 1;        // warp tile 64x32 at (wm*64, wn*32)
    const int row0 = blockIdx.x * BM;

    // coalesced zero-fill of this block's output tile [128 x 64]
    {
        float4 z = make_float4(0.f, 0.f, 0.f, 0.f);
        float4* ot = (float4*)(out + (size_t)row0 * NE);
        #pragma unroll
        for (int i = 0; i < 8; ++i) ot[tid + 256 * i] = z;
    }

    // ldmatrix per-thread bases (swizzle: column-bytes XOR (row&7)<<4)
    const int rA = wm * 64 + (lane & 15);
    const uint32_t xorA = (uint32_t)((rA & 7) << 4);
    const uint32_t cbA = (uint32_t)((lane >> 4) * 16);
    const int rB = wn * 32 + (lane & 7) + ((lane >> 4) << 3);
    const uint32_t xorB = (uint32_t)((rB & 7) << 4);
    const uint32_t cbB = (uint32_t)(((lane >> 3) & 1) * 16);

    const int r_x = tid >> 1;           // x row this thread stages/converts
    const int h_x = tid & 1;            // k half (32 floats)

    // cp.async issue helper values
    const float* xbase = x + (size_t)(row0 + r_x) * DK + h_x * 32;

    float acc[4][4][4];
    #pragma unroll
    for (int mt = 0; mt < 4; ++mt)
        #pragma unroll
        for (int nt = 0; nt < 4; ++nt)
            #pragma unroll
            for (int q = 0; q < 4; ++q) acc[mt][nt][q] = 0.f;

    // ---- prologue: stage chunk 0 ----
    {
        uint32_t xdst = sb + OFF_X + (uint32_t)(r_x * XROW_B + h_x * 128);
        #pragma unroll
        for (int i = 0; i < 8; ++i) cp16(xdst + 16 * i, xbase + 4 * i);
        #pragma unroll
        for (int j = 0; j < 8; ++j) {
            const int u = tid + 256 * j;            // 0..2047
            const int s = u >> 10, rem = u & 1023;
            const int n = rem >> 3, cu = rem & 7;
            uint32_t off = (uint32_t)(n * 128 + cu * 16);
            uint32_t sw = off ^ (((uint32_t)(n & 7)) << 4);
            cp16(sb + OFF_B + s * PLANE_B + sw, &g_w[s][n * DK + cu * 8]);
        }
        asm volatile("cp.async.commit_group;" ::: "memory");
    }

    for (int c = 0; c < NCHUNK; ++c) {
        const int b = c & 1;
        asm volatile("cp.async.wait_group 0;" ::: "memory");
        __syncthreads();   // stage c ready; MMA c-1 done (A + stage 1-b free)

        // ---- convert staged fp32 x -> split fp16 A planes (swizzled) ----
        {
            const float* xs = (const float*)(smem + OFF_X + b * XSTAGE_B + r_x * XROW_B + h_x * 128);
            #pragma unroll
            for (int i = 0; i < 8; ++i) {
                float4 v = *(const float4*)(xs + 4 * i);
                uint32_t off = (uint32_t)(r_x * 128 + (h_x * 32 + 4 * i) * 2);
                uint32_t sw = off ^ (((uint32_t)(r_x & 7)) << 4);
                float f[4] = {v.x, v.y, v.z, v.w};
                __half hh[4], hl[4];
                #pragma unroll
                for (int j = 0; j < 4; ++j) {
                    hh[j] = __float2half_rn(f[j]);
                    hl[j] = __float2half_rn(f[j] - __half2float(hh[j]));
                }
                *(uint2*)(smem + OFF_A + sw) =
                    make_uint2(pack_h2(hh[0], hh[1]), pack_h2(hh[2], hh[3]));
                *(uint2*)(smem + OFF_A + PLANE_B + sw) =
                    make_uint2(pack_h2(hl[0], hl[1]), pack_h2(hl[2], hl[3]));
            }
        }

        // ---- prefetch chunk c+1 into buffers 1-b ----
        if (c + 1 < NCHUNK) {
            const int k1 = (c + 1) * KC;
            uint32_t xdst = sb + OFF_X + (uint32_t)((1 - b) * XSTAGE_B + r_x * XROW_B + h_x * 128);
            const float* xsrc = xbase + k1;
            #pragma unroll
            for (int i = 0; i < 8; ++i) cp16(xdst + 16 * i, xsrc + 4 * i);
            #pragma unroll
            for (int j = 0; j < 8; ++j) {
                const int u = tid + 256 * j;
                const int s = u >> 10, rem = u & 1023;
                const int n = rem >> 3, cu = rem & 7;
                uint32_t off = (uint32_t)(n * 128 + cu * 16);
                uint32_t sw = off ^ (((uint32_t)(n & 7)) << 4);
                cp16(sb + OFF_B + ((1 - b) * 2 + s) * PLANE_B + sw,
                     &g_w[s][n * DK + k1 + cu * 8]);
            }
        }
        asm volatile("cp.async.commit_group;" ::: "memory");
        __syncthreads();   // A planes written, safe to ldmatrix

        // ---- 3 split products, k16 steps; B from buffer b ----
        const uint32_t sbAh = sb + OFF_A;
        const uint32_t sbAl = sb + OFF_A + PLANE_B;
        const uint32_t sbBh = sb + OFF_B + (uint32_t)(b * 2) * PLANE_B;
        const uint32_t sbBl = sbBh + PLANE_B;
        #pragma unroll 1
        for (int ks = 0; ks < 4; ++ks) {
            const uint32_t kb = (uint32_t)(ks * 32);
            uint32_t a[4][4], bh[8], bl[8];
            #pragma unroll
            for (int mt = 0; mt < 4; ++mt)
                ldsm4(a[mt][0], a[mt][1], a[mt][2], a[mt][3],
                      sbAh + (rA + mt * 16) * 128 + ((kb + cbA) ^ xorA));
            ldsm4(bh[0], bh[1], bh[2], bh[3], sbBh + rB * 128 + ((kb + cbB) ^ xorB));
            ldsm4(bh[4], bh[5], bh[6], bh[7], sbBh + (rB + 16) * 128 + ((kb + cbB) ^ xorB));
            ldsm4(bl[0], bl[1], bl[2], bl[3], sbBl + rB * 128 + ((kb + cbB) ^ xorB));
            ldsm4(bl[4], bl[5], bl[6], bl[7], sbBl + (rB + 16) * 128 + ((kb + cbB) ^ xorB));
            #pragma unroll
            for (int mt = 0; mt < 4; ++mt)
                #pragma unroll
                for (int nt = 0; nt < 4; ++nt)
                    mma16816(acc[mt][nt], a[mt][0], a[mt][1], a[mt][2], a[mt][3],
                             bh[2 * nt], bh[2 * nt + 1]);
            #pragma unroll
            for (int mt = 0; mt < 4; ++mt)
                #pragma unroll
                for (int nt = 0; nt < 4; ++nt)
                    mma16816(acc[mt][nt], a[mt][0], a[mt][1], a[mt][2], a[mt][3],
                             bl[2 * nt], bl[2 * nt + 1]);
            #pragma unroll
            for (int mt = 0; mt < 4; ++mt)
                ldsm4(a[mt][0], a[mt][1], a[mt][2], a[mt][3],
                      sbAl + (rA + mt * 16) * 128 + ((kb + cbA) ^ xorA));
            #pragma unroll
            for (int mt = 0; mt < 4; ++mt)
                #pragma unroll
                for (int nt = 0; nt < 4; ++nt)
                    mma16816(acc[mt][nt], a[mt][0], a[mt][1], a[mt][2], a[mt][3],
                             bh[2 * nt], bh[2 * nt + 1]);
        }
    }
    __syncthreads();

    // ---- stage C (scaled by 1/32) + eps to smem, fused top-2 epilogue ----
    float* Cs = (float*)smem;                    // [128][130]
    float* Es = (float*)(smem + 66560);          // [128][66]
    {
        const float INV32 = 0.03125f;
        const int crow = wm * 64 + (lane >> 2);
        const int ccol = wn * 32 + (lane & 3) * 2;
        #pragma unroll
        for (int mt = 0; mt < 4; ++mt)
            #pragma unroll
            for (int nt = 0; nt < 4; ++nt) {
                float* p0 = Cs + (crow + mt * 16) * 130 + ccol + nt * 8;
                p0[0] = acc[mt][nt][0] * INV32; p0[1] = acc[mt][nt][1] * INV32;
                float* p1 = p0 + 8 * 130;
                p1[0] = acc[mt][nt][2] * INV32; p1[1] = acc[mt][nt][3] * INV32;
            }
        const float4* eg = (const float4*)(eps + (size_t)row0 * NE);
        #pragma unroll
        for (int i4 = 0; i4 < 8; ++i4) {
            int u = tid + 256 * i4;                 // 0..2047
            float4 v = eg[u];
            int r = u >> 4, e = (u & 15) * 4;
            float* d = Es + r * 66 + e;
            d[0] = v.x; d[1] = v.y; d[2] = v.z; d[3] = v.w;
        }
    }
    __syncthreads();

    if (tid < BM) {
        const int r = tid;
        const size_t n = (size_t)row0 + r;
        const float* lg = Cs + r * 130;
        const float* er = Es + r * 66;
        const float NEG = __int_as_float(0xff800000);
        float m1 = NEG, m2 = NEG; int i1 = 0, i2 = 0;
        #pragma unroll
        for (int e = 0; e < NE; ++e) {
            float v = lg[e] + er[e] * softplusf(lg[e + 64]);
            if (v > m1) { m2 = m1; i2 = i1; m1 = v; i1 = e; }
            else if (v > m2) { m2 = v; i2 = e; }
        }
        float ee = expf(m2 - m1);
        float inv = 1.0f / (1.0f + ee);
        out[n * NE + i1] = inv;
        out[n * NE + i2] = ee * inv;
        if (write_idx) {
            idx_out[n * 2 + 0] = (float)i1;
            idx_out[n * 2 + 1] = (float)i2;
        }
    }
}

extern "C" void kernel_launch(void* const* d_in, const int* in_sizes, int n_in,
                              void* d_out, int out_size)
{
    const float* x   = (const float*)d_in[0];
    const float* wr  = (const float*)d_in[1];
    const float* wn  = (const float*)d_in[2];
    const float* eps = (const float*)d_in[3];
    float* out = (float*)d_out;

    const int N = in_sizes[3] / NE;
    const int write_idx = (out_size >= N * NE + N * 2) ? 1 : 0;
    float* idx_out = out + (size_t)N * NE;

    prep_weights<<<(128 * DK) / 256, 256>>>(wr, wn);

    cudaFuncSetAttribute(router_gemm,
                         cudaFuncAttributeMaxDynamicSharedMemorySize, SMEM_BYTES);
    router_gemm<<<N / BM, 256, SMEM_BYTES>>>(x, eps, out, idx_out, write_idx);
}

// round 5
// speedup vs baseline: 2.7018x; 1.4984x over previous
#include <cuda_runtime.h>
#include <cuda_fp16.h>
#include <cstdint>

// TopKNoisyRouter: fused dual GEMM [N,1024]x[1024,128], fp16 2-way split
// (3 HMMA products, fp32 accum, W pre-scaled by 32), KC=32 double-buffered
// pipeline (x via LDG->reg->convert->STS, B via cp.async), 2 CTAs/SM,
// one barrier per chunk, fused noisy-top-2 + softmax epilogue.

#define DK 1024
#define NE 64
#define BM 128
#define KC 32
#define NCHUNK (DK / KC)      // 32
#define PLANE 8192            // 128 rows x 32 fp16 (64B rows)
#define OFF_B (4 * PLANE)     // A: 2 bufs x 2 planes; B: same, after A
#define SMEM_BYTES 100352     // max(gemm 64KB, epilogue C+eps staging)

// Pre-split scaled weights: g_w[0]=fp16(32w), g_w[1]=fp16(32w - hi). K-major,
// rows 0..63 route, 64..127 noise.
__device__ __half g_w[2][128 * DK];

__device__ __forceinline__ uint32_t smem_u32(const void* p) {
    uint32_t a;
    asm("{ .reg .u64 t; cvta.to.shared.u64 t, %1; cvt.u32.u64 %0, t; }" : "=r"(a) : "l"(p));
    return a;
}
// 64B-row conflict-free layout: row r, col-byte c (0..63)
__device__ __forceinline__ uint32_t swz32(uint32_t r, uint32_t c) {
    return (r >> 1) * 128 + (r & 1) * 64 + (c ^ (((r >> 1) & 3) << 4));
}
__device__ __forceinline__ void cp16(uint32_t dst, const void* src) {
    asm volatile("cp.async.cg.shared.global [%0], [%1], 16;" :: "r"(dst), "l"(src));
}
__device__ __forceinline__ void ldsm4(uint32_t& r0, uint32_t& r1, uint32_t& r2,
                                      uint32_t& r3, uint32_t addr) {
    asm volatile("ldmatrix.sync.aligned.m8n8.x4.shared.b16 {%0,%1,%2,%3}, [%4];"
                 : "=r"(r0), "=r"(r1), "=r"(r2), "=r"(r3) : "r"(addr));
}
__device__ __forceinline__ void mma16816(float* c, const uint32_t* a,
                                         uint32_t b0, uint32_t b1) {
    asm volatile("mma.sync.aligned.m16n8k16.row.col.f32.f16.f16.f32 "
                 "{%0,%1,%2,%3}, {%4,%5,%6,%7}, {%8,%9}, {%0,%1,%2,%3};"
                 : "+f"(c[0]), "+f"(c[1]), "+f"(c[2]), "+f"(c[3])
                 : "r"(a[0]), "r"(a[1]), "r"(a[2]), "r"(a[3]), "r"(b0), "r"(b1));
}
__device__ __forceinline__ float softplusf(float v) {
    return fmaxf(v, 0.0f) + log1pf(expf(-fabsf(v)));
}
__device__ __forceinline__ uint32_t pack_h2(__half lo, __half hi) {
    return (uint32_t)__half_as_ushort(lo) | ((uint32_t)__half_as_ushort(hi) << 16);
}

__global__ void prep_weights(const float* __restrict__ wr, const float* __restrict__ wn) {
    int i = blockIdx.x * blockDim.x + threadIdx.x;    // 0 .. 128*1024-1
    int e = i >> 10, k = i & 1023;
    float v = 32.0f * ((e < NE) ? wr[e * DK + k] : wn[(e - NE) * DK + k]);
    __half h = __float2half_rn(v);
    g_w[0][i] = h;
    g_w[1][i] = __float2half_rn(v - __half2float(h));
}

__global__ __launch_bounds__(256, 2)
void router_gemm(const float* __restrict__ x, const float* __restrict__ eps,
                 float* __restrict__ out, float* __restrict__ idx_out, int write_idx)
{
    extern __shared__ char smem[];
    const uint32_t sb = smem_u32(smem);
    const int tid = threadIdx.x;
    const int lane = tid & 31, wid = tid >> 5;
    const int wm = wid & 1, wq = wid >> 1;        // warp tile 64x32 at (wm*64, wq*32)
    const int row0 = blockIdx.x * BM;

    // coalesced zero-fill of this block's output tile [128 x 64]
    {
        float4 z = make_float4(0.f, 0.f, 0.f, 0.f);
        float4* ot = (float4*)(out + (size_t)row0 * NE);
        #pragma unroll
        for (int i = 0; i < 8; ++i) ot[tid + 256 * i] = z;
    }

    // ldmatrix per-lane address pieces
    const int rA = wm * 64 + (lane & 15);
    const uint32_t rowA = (uint32_t)((rA >> 1) * 128 + (rA & 1) * 64);
    const uint32_t xorA = (uint32_t)(((rA >> 1) & 3) << 4);
    const uint32_t cbA  = (uint32_t)((lane >> 4) * 16);
    const int rB = wq * 32 + (lane & 7) + ((lane >> 4) << 3);
    const uint32_t rowB = (uint32_t)((rB >> 1) * 128 + (rB & 1) * 64);
    const uint32_t xorB = (uint32_t)(((rB >> 1) & 3) << 4);
    const uint32_t cbB  = (uint32_t)(((lane >> 3) & 1) * 16);

    // x staging: thread covers row r_x, 16 floats at float-offset h_x
    const int r_x = tid >> 1;
    const int h_x = (tid & 1) * 16;
    const float* xbase = x + (size_t)(row0 + r_x) * DK + h_x;
    const uint32_t rowX = (uint32_t)((r_x >> 1) * 128 + (r_x & 1) * 64);
    const uint32_t xorX = (uint32_t)(((r_x >> 1) & 3) << 4);

    float acc[4][4][4];
    #pragma unroll
    for (int mt = 0; mt < 4; ++mt)
        #pragma unroll
        for (int nt = 0; nt < 4; ++nt)
            #pragma unroll
            for (int q = 0; q < 4; ++q) acc[mt][nt][q] = 0.f;

    // ---- prologue: x chunk 0 -> regs; B chunk 0 -> cp.async ----
    float4 xr[4];
    #pragma unroll
    for (int i = 0; i < 4; ++i) xr[i] = *(const float4*)(xbase + 4 * i);
    {
        #pragma unroll
        for (int j = 0; j < 4; ++j) {
            const int u = tid + 256 * j;             // 0..1023
            const int s = u >> 9, rem = u & 511;
            const int n = rem >> 2, cu = (rem & 3) * 16;
            cp16(sb + OFF_B + (uint32_t)s * PLANE + swz32(n, cu),
                 &g_w[s][n * DK + (cu >> 1)]);
        }
        asm volatile("cp.async.commit_group;" ::: "memory");
    }

    for (int c = 0; c < NCHUNK; ++c) {
        const int b = c & 1;
        const int kn = ((c + 1) & (NCHUNK - 1)) * KC;   // next chunk (wraps, safe)
        char* Ab = smem + (uint32_t)(b * 2) * PLANE;

        // ---- convert x regs -> A[b] planes; prefetch next x into regs ----
        #pragma unroll
        for (int i = 0; i < 4; ++i) {
            float4 f4 = xr[i];
            xr[i] = *(const float4*)(xbase + kn + 4 * i);
            const uint32_t cb = (uint32_t)((h_x + 4 * i) * 2);
            const uint32_t sw = rowX + (cb ^ xorX);
            float f[4] = {f4.x, f4.y, f4.z, f4.w};
            __half hh[4], hl[4];
            #pragma unroll
            for (int j = 0; j < 4; ++j) {
                hh[j] = __float2half_rn(f[j]);
                hl[j] = __float2half_rn(f[j] - __half2float(hh[j]));
            }
            *(uint2*)(Ab + sw)         = make_uint2(pack_h2(hh[0], hh[1]), pack_h2(hh[2], hh[3]));
            *(uint2*)(Ab + PLANE + sw) = make_uint2(pack_h2(hl[0], hl[1]), pack_h2(hl[2], hl[3]));
        }

        asm volatile("cp.async.wait_group 0;" ::: "memory");   // B[b] ready
        __syncthreads();                                        // A[b] visible

        // ---- prefetch B for next chunk into buffer 1-b ----
        #pragma unroll
        for (int j = 0; j < 4; ++j) {
            const int u = tid + 256 * j;
            const int s = u >> 9, rem = u & 511;
            const int n = rem >> 2, cu = (rem & 3) * 16;
            cp16(sb + OFF_B + (uint32_t)((1 - b) * 2 + s) * PLANE + swz32(n, cu),
                 &g_w[s][n * DK + kn + (cu >> 1)]);
        }
        asm volatile("cp.async.commit_group;" ::: "memory");

        // ---- MMA: 3 split products over 2 k16 steps ----
        const uint32_t Ah = sb + (uint32_t)(b * 2) * PLANE;
        const uint32_t Al = Ah + PLANE;
        const uint32_t Bh = sb + OFF_B + (uint32_t)(b * 2) * PLANE;
        const uint32_t Bl = Bh + PLANE;
        #pragma unroll
        for (int ks = 0; ks < 2; ++ks) {
            const uint32_t kb = (uint32_t)(ks * 32);
            const uint32_t ca = (kb + cbA) ^ xorA;
            const uint32_t cbb = (kb + cbB) ^ xorB;
            uint32_t a[4][4], bh[8], bl[8];
            #pragma unroll
            for (int mt = 0; mt < 4; ++mt)
                ldsm4(a[mt][0], a[mt][1], a[mt][2], a[mt][3],
                      Ah + rowA + mt * 1024 + ca);
            ldsm4(bh[0], bh[1], bh[2], bh[3], Bh + rowB + cbb);
            ldsm4(bh[4], bh[5], bh[6], bh[7], Bh + rowB + 1024 + cbb);
            ldsm4(bl[0], bl[1], bl[2], bl[3], Bl + rowB + cbb);
            ldsm4(bl[4], bl[5], bl[6], bl[7], Bl + rowB + 1024 + cbb);
            #pragma unroll
            for (int mt = 0; mt < 4; ++mt)
                #pragma unroll
                for (int nt = 0; nt < 4; ++nt)
                    mma16816(acc[mt][nt], a[mt], bh[2 * nt], bh[2 * nt + 1]);
            #pragma unroll
            for (int mt = 0; mt < 4; ++mt)
                #pragma unroll
                for (int nt = 0; nt < 4; ++nt)
                    mma16816(acc[mt][nt], a[mt], bl[2 * nt], bl[2 * nt + 1]);
            #pragma unroll
            for (int mt = 0; mt < 4; ++mt)
                ldsm4(a[mt][0], a[mt][1], a[mt][2], a[mt][3],
                      Al + rowA + mt * 1024 + ca);
            #pragma unroll
            for (int mt = 0; mt < 4; ++mt)
                #pragma unroll
                for (int nt = 0; nt < 4; ++nt)
                    mma16816(acc[mt][nt], a[mt], bh[2 * nt], bh[2 * nt + 1]);
        }
    }
    __syncthreads();

    // ---- stage C (scaled 1/32) + eps to smem, fused top-2 epilogue ----
    float* Cs = (float*)smem;                    // [128][130]
    float* Es = (float*)(smem + 66560);          // [128][66]
    {
        const float INV32 = 0.03125f;
        const int crow = wm * 64 + (lane >> 2);
        const int ccol = wq * 32 + (lane & 3) * 2;
        #pragma unroll
        for (int mt = 0; mt < 4; ++mt)
            #pragma unroll
            for (int nt = 0; nt < 4; ++nt) {
                float* p0 = Cs + (crow + mt * 16) * 130 + ccol + nt * 8;
                p0[0] = acc[mt][nt][0] * INV32; p0[1] = acc[mt][nt][1] * INV32;
                float* p1 = p0 + 8 * 130;
                p1[0] = acc[mt][nt][2] * INV32; p1[1] = acc[mt][nt][3] * INV32;
            }
        const float4* eg = (const float4*)(eps + (size_t)row0 * NE);
        #pragma unroll
        for (int i4 = 0; i4 < 8; ++i4) {
            int u = tid + 256 * i4;                 // 0..2047
            float4 v = eg[u];
            int r = u >> 4, e = (u & 15) * 4;
            float* d = Es + r * 66 + e;
            d[0] = v.x; d[1] = v.y; d[2] = v.z; d[3] = v.w;
        }
    }
    __syncthreads();

    if (tid < BM) {
        const int r = tid;
        const size_t n = (size_t)row0 + r;
        const float* lg = Cs + r * 130;
        const float* er = Es + r * 66;
        const float NEG = __int_as_float(0xff800000);
        float m1 = NEG, m2 = NEG; int i1 = 0, i2 = 0;
        #pragma unroll
        for (int e = 0; e < NE; ++e) {
            float v = lg[e] + er[e] * softplusf(lg[e + 64]);
            if (v > m1) { m2 = m1; i2 = i1; m1 = v; i1 = e; }
            else if (v > m2) { m2 = v; i2 = e; }
        }
        float ee = expf(m2 - m1);
        float inv = 1.0f / (1.0f + ee);
        out[n * NE + i1] = inv;
        out[n * NE + i2] = ee * inv;
        if (write_idx) {
            idx_out[n * 2 + 0] = (float)i1;
            idx_out[n * 2 + 1] = (float)i2;
        }
    }
}

extern "C" void kernel_launch(void* const* d_in, const int* in_sizes, int n_in,
                              void* d_out, int out_size)
{
    const float* x   = (const float*)d_in[0];
    const float* wr  = (const float*)d_in[1];
    const float* wn  = (const float*)d_in[2];
    const float* eps = (const float*)d_in[3];
    float* out = (float*)d_out;

    const int N = in_sizes[3] / NE;
    const int write_idx = (out_size >= N * NE + N * 2) ? 1 : 0;
    float* idx_out = out + (size_t)N * NE;

    prep_weights<<<(128 * DK) / 256, 256>>>(wr, wn);

    cudaFuncSetAttribute(router_gemm,
                         cudaFuncAttributeMaxDynamicSharedMemorySize, SMEM_BYTES);
    router_gemm<<<N / BM, 256, SMEM_BYTES>>>(x, eps, out, idx_out, write_idx);
}